// round 1
// baseline (speedup 1.0000x reference)
#include <cuda_runtime.h>
#include <math.h>

#define NN   512
#define NP   (NN*NN)        // 262144
#define FIN  16
#define TWOF 32
#define HH   64
#define EE   16384
#define NL   3

// ---------------- scratch (device globals; no allocation allowed) ----------
__device__ float g_U [64u*NP];
__device__ float g_V [64u*NP];
__device__ float g_O1[64u*NP];
__device__ float g_O2[64u*NP];
__device__ float g_M [64u*NP];
__device__ float g_ST[256];   // [0:64) trace, [64:128) tot, [128:192) mean, [192:256) var
__device__ float g_AC[64];    // extractor accumulator

// ---------------- init: zero A (32 ch) + accumulator ------------------------
__global__ void k_zero(float* U, float* AC) {
    int i = blockIdx.x * 256 + threadIdx.x;           // 32*NP threads
    U[i] = 0.f;
    if (i < 64) AC[i] = 0.f;
}

// ---------------- scatter edges into A[c][src][dst] -------------------------
__global__ void k_scatter(const float* __restrict__ x, const int* __restrict__ ei,
                          float* __restrict__ A) {
    int t = blockIdx.x * 256 + threadIdx.x;           // EE*32 threads
    int e = t >> 5, c = t & 31;
    int s = ei[e], d = ei[EE + e];
    float v = (c < FIN) ? x[s * FIN + c] : x[d * FIN + (c - FIN)];
    atomicAdd(&A[(size_t)c * NP + s * NN + d], v);
}

// ---------------- per-channel trace + total sums ----------------------------
__global__ void k_ext_stats(const float* __restrict__ U, float* __restrict__ st) {
    int c = blockIdx.x;
    const float* u = U + (size_t)c * NP;
    float tot = 0.f, tr = 0.f;
    for (int i = threadIdx.x; i < NP;  i += 256) tot += u[i];
    for (int i = threadIdx.x; i < NN;  i += 256) tr  += u[i * (NN + 1)];
    __shared__ float s1[256], s2[256];
    s1[threadIdx.x] = tot; s2[threadIdx.x] = tr; __syncthreads();
    for (int o = 128; o > 0; o >>= 1) {
        if (threadIdx.x < o) { s1[threadIdx.x] += s1[threadIdx.x+o]; s2[threadIdx.x] += s2[threadIdx.x+o]; }
        __syncthreads();
    }
    if (threadIdx.x == 0) { st[c] = s2[0]; st[64 + c] = s1[0]; }
}

// ---------------- extractor combine (tiny) ----------------------------------
__global__ void k_ext_combine(const float* __restrict__ st,
                              const float* __restrict__ w1, const float* __restrict__ b1,
                              const float* __restrict__ w2, const float* __restrict__ w3,
                              int C, float* __restrict__ acc) {
    int h = threadIdx.x;                               // 64 threads
    __shared__ float osh[64];
    float o = b1[h];
    for (int c = 0; c < C; c++) {
        float tr = st[c];
        float s  = (st[64 + c] - tr) / (512.f * 511.f);
        o += w1[h * C + c] * (tr / 512.f) + w2[h * C + c] * s;
    }
    osh[h] = o; __syncthreads();
    float a = o;
    for (int k = 0; k < 64; k++) a += w3[h * 64 + k] * fmaxf(osh[k], 0.f);
    acc[h] += a;
}

// ---------------- channel mix: out[o][p] = b[o] + W[o,:]·[in1;in2][:, p] -----
__global__ __launch_bounds__(256) void k_mix(
    const float* __restrict__ in1, int C1,
    const float* __restrict__ in2, int C2,
    const float* __restrict__ W, const float* __restrict__ bias,
    float* __restrict__ out) {
    extern __shared__ float Wsh[];
    const int Ct = C1 + C2;
    for (int i = threadIdx.x; i < 64 * Ct; i += 256) Wsh[i] = W[i];
    __syncthreads();
    const int p0 = blockIdx.x * 512 + threadIdx.x;
    const int p1 = p0 + 256;
    float a0[64], a1[64];
#pragma unroll
    for (int o = 0; o < 64; o++) { float b = bias[o]; a0[o] = b; a1[o] = b; }
    for (int c = 0; c < C1; c++) {
        float v0 = in1[(size_t)c * NP + p0];
        float v1 = in1[(size_t)c * NP + p1];
        const float* wc = Wsh + c;
#pragma unroll
        for (int o = 0; o < 64; o++) { float w = wc[o * Ct]; a0[o] += w * v0; a1[o] += w * v1; }
    }
    for (int c = 0; c < C2; c++) {
        float v0 = in2[(size_t)c * NP + p0];
        float v1 = in2[(size_t)c * NP + p1];
        const float* wc = Wsh + C1 + c;
#pragma unroll
        for (int o = 0; o < 64; o++) { float w = wc[o * Ct]; a0[o] += w * v0; a1[o] += w * v1; }
    }
#pragma unroll
    for (int o = 0; o < 64; o++) {
        out[(size_t)o * NP + p0] = a0[o];
        out[(size_t)o * NP + p1] = a1[o];
    }
}

// ---------------- batched 512x512x512 fp32 SGEMM (per channel) ---------------
__global__ __launch_bounds__(256) void k_sgemm(const float* __restrict__ A,
                                               const float* __restrict__ B,
                                               float* __restrict__ C) {
    const int ch = blockIdx.z;
    const float* Ab = A + (size_t)ch * NP;
    const float* Bb = B + (size_t)ch * NP;
    float*       Cb = C + (size_t)ch * NP;
    __shared__ float As[16][128];
    __shared__ float Bs[16][128];
    const int tid = threadIdx.x;
    const int tx = tid & 15, ty = tid >> 4;
    const int rowBase = blockIdx.y * 128;
    const int colBase = blockIdx.x * 128;
    float acc[8][8];
#pragma unroll
    for (int i = 0; i < 8; i++)
#pragma unroll
        for (int j = 0; j < 8; j++) acc[i][j] = 0.f;

    for (int k0 = 0; k0 < NN; k0 += 16) {
#pragma unroll
        for (int l = 0; l < 2; l++) {
            int lin = tid + l * 256;
            int r  = lin >> 2;
            int kq = (lin & 3) << 2;
            float4 v = *(const float4*)(Ab + (size_t)(rowBase + r) * NN + k0 + kq);
            As[kq + 0][r] = v.x; As[kq + 1][r] = v.y; As[kq + 2][r] = v.z; As[kq + 3][r] = v.w;
        }
#pragma unroll
        for (int l = 0; l < 2; l++) {
            int lin = tid + l * 256;
            int kk = lin >> 5;
            int c4 = (lin & 31) << 2;
            *(float4*)(&Bs[kk][c4]) = *(const float4*)(Bb + (size_t)(k0 + kk) * NN + colBase + c4);
        }
        __syncthreads();
#pragma unroll
        for (int kk = 0; kk < 16; kk++) {
            float a[8], b[8];
            *(float4*)(a)     = *(const float4*)(&As[kk][ty * 8]);
            *(float4*)(a + 4) = *(const float4*)(&As[kk][ty * 8 + 4]);
            *(float4*)(b)     = *(const float4*)(&Bs[kk][tx * 8]);
            *(float4*)(b + 4) = *(const float4*)(&Bs[kk][tx * 8 + 4]);
#pragma unroll
            for (int i = 0; i < 8; i++)
#pragma unroll
                for (int j = 0; j < 8; j++) acc[i][j] += a[i] * b[j];
        }
        __syncthreads();
    }
#pragma unroll
    for (int i = 0; i < 8; i++) {
        float* cp = Cb + (size_t)(rowBase + ty * 8 + i) * NN + colBase + tx * 8;
        *(float4*)(cp)     = make_float4(acc[i][0], acc[i][1], acc[i][2], acc[i][3]);
        *(float4*)(cp + 4) = make_float4(acc[i][4], acc[i][5], acc[i][6], acc[i][7]);
    }
}

// ---------------- batchnorm stats + apply ------------------------------------
__global__ void k_bn_stats(const float* __restrict__ U, float* __restrict__ st) {
    int c = blockIdx.x;
    const float* u = U + (size_t)c * NP;
    float s = 0.f, q = 0.f;
    for (int i = threadIdx.x; i < NP; i += 256) { float v = u[i]; s += v; q += v * v; }
    __shared__ float s1[256], s2[256];
    s1[threadIdx.x] = s; s2[threadIdx.x] = q; __syncthreads();
    for (int o = 128; o > 0; o >>= 1) {
        if (threadIdx.x < o) { s1[threadIdx.x] += s1[threadIdx.x+o]; s2[threadIdx.x] += s2[threadIdx.x+o]; }
        __syncthreads();
    }
    if (threadIdx.x == 0) {
        float m = s1[0] / (float)NP;
        st[128 + c] = m;
        st[192 + c] = s2[0] / (float)NP - m * m;
    }
}

__global__ void k_bn_apply(float* __restrict__ U, const float* __restrict__ st,
                           const float* __restrict__ g, const float* __restrict__ b) {
    int i = blockIdx.x * 256 + threadIdx.x;            // 64*NP threads
    int c = i >> 18;
    float m   = st[128 + c];
    float inv = rsqrtf(st[192 + c] + 1e-5f);
    U[i] = (U[i] - m) * inv * g[c] + b[c];
}

// ---------------- head: after_conv + final linear + log_softmax --------------
__global__ void k_head(const float* __restrict__ acc,
                       const float* __restrict__ ac_w, const float* __restrict__ ac_b,
                       const float* __restrict__ fl_w, const float* __restrict__ fl_b,
                       float* __restrict__ out) {
    __shared__ float o[64], t[64], lg[10];
    int h = threadIdx.x;
    o[h] = fmaxf(acc[h], 0.f) / (float)NL;
    __syncthreads();
    float s = ac_b[h];
    for (int k = 0; k < 64; k++) s += ac_w[h * 64 + k] * o[k];
    t[h] = o[h] + fmaxf(s, 0.f);
    __syncthreads();
    if (h < 10) {
        float l = fl_b[h];
        for (int k = 0; k < 64; k++) l += fl_w[h * 64 + k] * t[k];
        lg[h] = l;
    }
    __syncthreads();
    if (h < 10) {
        float m = -1e30f;
        for (int i = 0; i < 10; i++) m = fmaxf(m, lg[i]);
        float se = 0.f;
        for (int i = 0; i < 10; i++) se += expf(lg[i] - m);
        out[h] = lg[h] - m - logf(se);
    }
}

// ---------------- launch -----------------------------------------------------
extern "C" void kernel_launch(void* const* d_in, const int* in_sizes, int n_in,
                              void* d_out, int out_size) {
    const float* x     = (const float*)d_in[0];
    const int*   ei    = (const int*)  d_in[1];
    const float* np1_w = (const float*)d_in[2];
    const float* np1_b = (const float*)d_in[3];
    const float* np2_w = (const float*)d_in[4];
    const float* np3_w = (const float*)d_in[5];
    const float* c0m1w = (const float*)d_in[6];
    const float* c0m1b = (const float*)d_in[7];
    const float* c0m2w = (const float*)d_in[8];
    const float* c0m2b = (const float*)d_in[9];
    const float* c0m4w = (const float*)d_in[10];
    const float* c0m4b = (const float*)d_in[11];
    const float* cm1w  = (const float*)d_in[12];
    const float* cm1b  = (const float*)d_in[13];
    const float* cm2w  = (const float*)d_in[14];
    const float* cm2b  = (const float*)d_in[15];
    const float* cm4w  = (const float*)d_in[16];
    const float* cm4b  = (const float*)d_in[17];
    const float* bn_g  = (const float*)d_in[18];
    const float* bn_b  = (const float*)d_in[19];
    const float* fe1w  = (const float*)d_in[20];
    const float* fe1b  = (const float*)d_in[21];
    const float* fe2w  = (const float*)d_in[22];
    const float* fe3w  = (const float*)d_in[23];
    const float* ac_w  = (const float*)d_in[24];
    const float* ac_b  = (const float*)d_in[25];
    const float* fl_w  = (const float*)d_in[26];
    const float* fl_b  = (const float*)d_in[27];

    float *U, *V, *O1, *O2, *M, *ST, *AC;
    cudaGetSymbolAddress((void**)&U,  g_U);
    cudaGetSymbolAddress((void**)&V,  g_V);
    cudaGetSymbolAddress((void**)&O1, g_O1);
    cudaGetSymbolAddress((void**)&O2, g_O2);
    cudaGetSymbolAddress((void**)&M,  g_M);
    cudaGetSymbolAddress((void**)&ST, g_ST);
    cudaGetSymbolAddress((void**)&AC, g_AC);

    // Build adjacency tensor A (32 channels) in g_U
    k_zero<<<(32u * NP) / 256, 256>>>(U, AC);
    k_scatter<<<(EE * 32) / 256, 256>>>(x, ei, U);

    // no_prop extractor
    k_ext_stats<<<TWOF, 256>>>(U, ST);
    k_ext_combine<<<1, 64>>>(ST, np1_w, np1_b, np2_w, np3_w, TWOF, AC);

    const float* cur = U;
    float*       nxt = V;
    for (int l = 0; l < NL; l++) {
        const int Cin = l ? 64 : TWOF;
        const float* m1w = l ? cm1w + (l - 1) * 64 * 64  : c0m1w;
        const float* m1b = l ? cm1b + (l - 1) * 64       : c0m1b;
        const float* m2w = l ? cm2w + (l - 1) * 64 * 64  : c0m2w;
        const float* m2b = l ? cm2b + (l - 1) * 64       : c0m2b;
        const float* m4w = l ? cm4w + (l - 1) * 64 * 128 : c0m4w;
        const float* m4b = l ? cm4b + (l - 1) * 64       : c0m4b;

        size_t sh1 = (size_t)64 * Cin * sizeof(float);
        k_mix<<<512, 256, sh1>>>(cur, Cin, nullptr, 0, m1w, m1b, O1);
        k_mix<<<512, 256, sh1>>>(cur, Cin, nullptr, 0, m2w, m2b, O2);

        k_sgemm<<<dim3(4, 4, 64), 256>>>(O1, O2, M);

        size_t sh4 = (size_t)64 * (64 + Cin) * sizeof(float);
        k_mix<<<512, 256, sh4>>>(M, 64, cur, Cin, m4w, m4b, nxt);

        k_bn_stats<<<64, 256>>>(nxt, ST);
        k_bn_apply<<<(64u * NP) / 256, 256>>>(nxt, ST, bn_g + 64 * l, bn_b + 64 * l);

        k_ext_stats<<<64, 256>>>(nxt, ST);
        k_ext_combine<<<1, 64>>>(ST, fe1w + l * 64 * 64, fe1b + l * 64,
                                 fe2w + l * 64 * 64, fe3w + l * 64 * 64, 64, AC);

        float* tmp = (float*)cur; cur = nxt; nxt = tmp;
    }

    k_head<<<1, 64>>>(AC, ac_w, ac_b, fl_w, fl_b, (float*)d_out);
}

// round 3
// speedup vs baseline: 2.7750x; 2.7750x over previous
#include <cuda_runtime.h>
#include <math.h>
#include <stdint.h>

#define NN   512
#define NP   (NN*NN)        // 262144
#define FIN  16
#define TWOF 32
#define HH   64
#define EE   16384
#define NL   3

// ---------------- scratch (device globals; no allocation allowed) ----------
__device__ float g_U [64u*NP];
__device__ float g_V [64u*NP];
__device__ float g_O1[64u*NP];
__device__ float g_O2[64u*NP];
__device__ float g_M [64u*NP];
__device__ float g_ST[256];   // [0:64) trace, [64:128) tot, [128:192) mean, [192:256) var
__device__ float g_AC[64];    // extractor accumulator

__device__ __forceinline__ uint32_t f2tf32(float x) {
    uint32_t r; asm("cvt.rna.tf32.f32 %0, %1;" : "=r"(r) : "f"(x)); return r;
}

#define MMA_TF32(d, a, b)                                                      \
    asm volatile(                                                              \
        "mma.sync.aligned.m16n8k8.row.col.f32.tf32.tf32.f32 "                  \
        "{%0,%1,%2,%3},{%4,%5,%6,%7},{%8,%9},{%0,%1,%2,%3};"                   \
        : "+f"(d[0]), "+f"(d[1]), "+f"(d[2]), "+f"(d[3])                       \
        : "r"(a[0]), "r"(a[1]), "r"(a[2]), "r"(a[3]), "r"(b[0]), "r"(b[1]))

// ---------------- init: zero A (32 ch) + accumulator ------------------------
__global__ void k_zero(float* U, float* AC) {
    int i = blockIdx.x * 256 + threadIdx.x;           // 32*NP threads
    U[i] = 0.f;
    if (i < 64) AC[i] = 0.f;
}

// ---------------- scatter edges into A[c][src][dst] -------------------------
__global__ void k_scatter(const float* __restrict__ x, const int* __restrict__ ei,
                          float* __restrict__ A) {
    int t = blockIdx.x * 256 + threadIdx.x;           // EE*32 threads
    int e = t >> 5, c = t & 31;
    int s = ei[e], d = ei[EE + e];
    float v = (c < FIN) ? x[s * FIN + c] : x[d * FIN + (c - FIN)];
    atomicAdd(&A[(size_t)c * NP + s * NN + d], v);
}

// ---------------- per-channel trace + total sums ----------------------------
__global__ void k_ext_stats(const float* __restrict__ U, float* __restrict__ st) {
    int c = blockIdx.x;
    const float* u = U + (size_t)c * NP;
    float tot = 0.f, tr = 0.f;
    for (int i = threadIdx.x; i < NP;  i += 256) tot += u[i];
    for (int i = threadIdx.x; i < NN;  i += 256) tr  += u[i * (NN + 1)];
    __shared__ float s1[256], s2[256];
    s1[threadIdx.x] = tot; s2[threadIdx.x] = tr; __syncthreads();
    for (int o = 128; o > 0; o >>= 1) {
        if (threadIdx.x < o) { s1[threadIdx.x] += s1[threadIdx.x+o]; s2[threadIdx.x] += s2[threadIdx.x+o]; }
        __syncthreads();
    }
    if (threadIdx.x == 0) { st[c] = s2[0]; st[64 + c] = s1[0]; }
}

// ---------------- extractor combine (tiny) ----------------------------------
__global__ void k_ext_combine(const float* __restrict__ st,
                              const float* __restrict__ w1, const float* __restrict__ b1,
                              const float* __restrict__ w2, const float* __restrict__ w3,
                              int C, float* __restrict__ acc) {
    int h = threadIdx.x;                               // 64 threads
    __shared__ float osh[64];
    float o = b1[h];
    for (int c = 0; c < C; c++) {
        float tr = st[c];
        float s  = (st[64 + c] - tr) / (512.f * 511.f);
        o += w1[h * C + c] * (tr / 512.f) + w2[h * C + c] * s;
    }
    osh[h] = o; __syncthreads();
    float a = o;
    for (int k = 0; k < 64; k++) a += w3[h * 64 + k] * fmaxf(osh[k], 0.f);
    acc[h] += a;
}

// ---------------- channel mix via tf32 tensor cores --------------------------
// out[64][NP] = W[64][Ct] @ concat(in1,in2)[Ct][NP] + bias
// Block: 256 threads, 256 positions. Warp w covers cols [w*32, w*32+32).
__global__ __launch_bounds__(256) void k_mix_mma(
    const float* __restrict__ in1, int C1,
    const float* __restrict__ in2, int C2,
    const float* __restrict__ W, const float* __restrict__ bias,
    float* __restrict__ out) {
    const int Ct = C1 + C2;
    const int ld = Ct + 4;                 // ld % 32 == 4 -> conflict-free A frags
    extern __shared__ float sh[];
    float* Ws = sh;                        // [64][ld] tf32
    float* Us = sh + 64 * ld;              // [32][264] tf32

    for (int i = threadIdx.x; i < 64 * Ct; i += 256) {
        int o = i / Ct, c = i - o * Ct;
        Ws[o * ld + c] = __uint_as_float(f2tf32(W[i]));
    }

    const int p0   = blockIdx.x * 256;
    const int lane = threadIdx.x & 31;
    const int wid  = threadIdx.x >> 5;
    const int lq = lane & 3, lr = lane >> 2;

    float acc[4][4][4];
#pragma unroll
    for (int mi = 0; mi < 4; mi++)
#pragma unroll
        for (int nj = 0; nj < 4; nj++)
#pragma unroll
            for (int q = 0; q < 4; q++) acc[mi][nj][q] = 0.f;

    for (int k0 = 0; k0 < Ct; k0 += 32) {
        __syncthreads();
        for (int i = threadIdx.x; i < 32 * 64; i += 256) {    // 2048 float4
            int kk = i >> 6, c4 = (i & 63) << 2;
            int c = k0 + kk;
            const float* src = (c < C1) ? in1 + (size_t)c * NP
                                        : in2 + (size_t)(c - C1) * NP;
            float4 v = *(const float4*)(src + p0 + c4);
            float* d = Us + kk * 264 + c4;
            d[0] = __uint_as_float(f2tf32(v.x));
            d[1] = __uint_as_float(f2tf32(v.y));
            d[2] = __uint_as_float(f2tf32(v.z));
            d[3] = __uint_as_float(f2tf32(v.w));
        }
        __syncthreads();
#pragma unroll
        for (int kk = 0; kk < 32; kk += 8) {
            uint32_t a[4][4], b[4][2];
#pragma unroll
            for (int mi = 0; mi < 4; mi++) {
                int r = mi * 16 + lr;
                a[mi][0] = __float_as_uint(Ws[r * ld + k0 + kk + lq]);
                a[mi][1] = __float_as_uint(Ws[(r + 8) * ld + k0 + kk + lq]);
                a[mi][2] = __float_as_uint(Ws[r * ld + k0 + kk + 4 + lq]);
                a[mi][3] = __float_as_uint(Ws[(r + 8) * ld + k0 + kk + 4 + lq]);
            }
#pragma unroll
            for (int nj = 0; nj < 4; nj++) {
                int c = wid * 32 + nj * 8 + lr;
                b[nj][0] = __float_as_uint(Us[(kk + lq) * 264 + c]);
                b[nj][1] = __float_as_uint(Us[(kk + 4 + lq) * 264 + c]);
            }
#pragma unroll
            for (int mi = 0; mi < 4; mi++)
#pragma unroll
                for (int nj = 0; nj < 4; nj++) MMA_TF32(acc[mi][nj], a[mi], b[nj]);
        }
    }

#pragma unroll
    for (int mi = 0; mi < 4; mi++) {
        int o0 = mi * 16 + lr, o1 = o0 + 8;
        float b0 = bias[o0], b1 = bias[o1];
#pragma unroll
        for (int nj = 0; nj < 4; nj++) {
            int col = p0 + wid * 32 + nj * 8 + 2 * lq;
            float2 v0 = make_float2(acc[mi][nj][0] + b0, acc[mi][nj][1] + b0);
            float2 v1 = make_float2(acc[mi][nj][2] + b1, acc[mi][nj][3] + b1);
            *(float2*)(out + (size_t)o0 * NP + col) = v0;
            *(float2*)(out + (size_t)o1 * NP + col) = v1;
        }
    }
}

// ---------------- batched 512x512x512 tf32 tensor-core GEMM ------------------
// C[ch] = A[ch] @ B[ch], 128x128 block tile, 8 warps (32x64 warp tiles)
__global__ __launch_bounds__(256) void k_mma(const float* __restrict__ A,
                                             const float* __restrict__ B,
                                             float* __restrict__ C) {
    const int ch = blockIdx.z;
    const float* Ab = A + (size_t)ch * NP;
    const float* Bb = B + (size_t)ch * NP;
    float*       Cb = C + (size_t)ch * NP;
    __shared__ float As[128 * 36];     // [row][k], ld=36 (36%32==4: conflict-free)
    __shared__ float Bs[32 * 136];     // [k][col], ld=136 (136%32==8: conflict-free)
    const int tid  = threadIdx.x;
    const int lane = tid & 31, wid = tid >> 5;
    const int wr = wid >> 1, wc = wid & 1;     // 4x1 row groups x 2 col groups
    const int lq = lane & 3, lr = lane >> 2;
    const int rowBase = blockIdx.y * 128;
    const int colBase = blockIdx.x * 128;

    float acc[2][8][4];
#pragma unroll
    for (int mi = 0; mi < 2; mi++)
#pragma unroll
        for (int nj = 0; nj < 8; nj++)
#pragma unroll
            for (int q = 0; q < 4; q++) acc[mi][nj][q] = 0.f;

    for (int k0 = 0; k0 < NN; k0 += 32) {
#pragma unroll
        for (int i = 0; i < 4; i++) {            // A: 128x32 = 1024 float4
            int lin = tid + i * 256;
            int r = lin >> 3, k4 = (lin & 7) << 2;
            float4 v = *(const float4*)(Ab + (size_t)(rowBase + r) * NN + k0 + k4);
            float* d = As + r * 36 + k4;
            d[0] = __uint_as_float(f2tf32(v.x));
            d[1] = __uint_as_float(f2tf32(v.y));
            d[2] = __uint_as_float(f2tf32(v.z));
            d[3] = __uint_as_float(f2tf32(v.w));
        }
#pragma unroll
        for (int i = 0; i < 4; i++) {            // B: 32x128 = 1024 float4
            int lin = tid + i * 256;
            int kk = lin >> 5, c4 = (lin & 31) << 2;
            float4 v = *(const float4*)(Bb + (size_t)(k0 + kk) * NN + colBase + c4);
            float* d = Bs + kk * 136 + c4;
            d[0] = __uint_as_float(f2tf32(v.x));
            d[1] = __uint_as_float(f2tf32(v.y));
            d[2] = __uint_as_float(f2tf32(v.z));
            d[3] = __uint_as_float(f2tf32(v.w));
        }
        __syncthreads();
#pragma unroll
        for (int kk = 0; kk < 32; kk += 8) {
            uint32_t a[2][4], b[8][2];
#pragma unroll
            for (int mi = 0; mi < 2; mi++) {
                int r = wr * 32 + mi * 16 + lr;
                a[mi][0] = __float_as_uint(As[r * 36 + kk + lq]);
                a[mi][1] = __float_as_uint(As[(r + 8) * 36 + kk + lq]);
                a[mi][2] = __float_as_uint(As[r * 36 + kk + 4 + lq]);
                a[mi][3] = __float_as_uint(As[(r + 8) * 36 + kk + 4 + lq]);
            }
#pragma unroll
            for (int nj = 0; nj < 8; nj++) {
                int c = wc * 64 + nj * 8 + lr;
                b[nj][0] = __float_as_uint(Bs[(kk + lq) * 136 + c]);
                b[nj][1] = __float_as_uint(Bs[(kk + 4 + lq) * 136 + c]);
            }
#pragma unroll
            for (int mi = 0; mi < 2; mi++)
#pragma unroll
                for (int nj = 0; nj < 8; nj++) MMA_TF32(acc[mi][nj], a[mi], b[nj]);
        }
        __syncthreads();
    }

#pragma unroll
    for (int mi = 0; mi < 2; mi++) {
        int r0 = rowBase + wr * 32 + mi * 16 + lr;
#pragma unroll
        for (int nj = 0; nj < 8; nj++) {
            int col = colBase + wc * 64 + nj * 8 + 2 * lq;
            *(float2*)(Cb + (size_t)r0 * NN + col) =
                make_float2(acc[mi][nj][0], acc[mi][nj][1]);
            *(float2*)(Cb + (size_t)(r0 + 8) * NN + col) =
                make_float2(acc[mi][nj][2], acc[mi][nj][3]);
        }
    }
}

// ---------------- batchnorm stats + apply ------------------------------------
__global__ void k_bn_stats(const float* __restrict__ U, float* __restrict__ st) {
    int c = blockIdx.x;
    const float* u = U + (size_t)c * NP;
    float s = 0.f, q = 0.f;
    for (int i = threadIdx.x; i < NP; i += 256) { float v = u[i]; s += v; q += v * v; }
    __shared__ float s1[256], s2[256];
    s1[threadIdx.x] = s; s2[threadIdx.x] = q; __syncthreads();
    for (int o = 128; o > 0; o >>= 1) {
        if (threadIdx.x < o) { s1[threadIdx.x] += s1[threadIdx.x+o]; s2[threadIdx.x] += s2[threadIdx.x+o]; }
        __syncthreads();
    }
    if (threadIdx.x == 0) {
        float m = s1[0] / (float)NP;
        st[128 + c] = m;
        st[192 + c] = s2[0] / (float)NP - m * m;
    }
}

__global__ void k_bn_apply(float* __restrict__ U, const float* __restrict__ st,
                           const float* __restrict__ g, const float* __restrict__ b) {
    int i = blockIdx.x * 256 + threadIdx.x;            // 64*NP threads
    int c = i >> 18;
    float m   = st[128 + c];
    float inv = rsqrtf(st[192 + c] + 1e-5f);
    U[i] = (U[i] - m) * inv * g[c] + b[c];
}

// ---------------- head: after_conv + final linear + log_softmax --------------
__global__ void k_head(const float* __restrict__ acc,
                       const float* __restrict__ ac_w, const float* __restrict__ ac_b,
                       const float* __restrict__ fl_w, const float* __restrict__ fl_b,
                       float* __restrict__ out) {
    __shared__ float o[64], t[64], lg[10];
    int h = threadIdx.x;
    o[h] = fmaxf(acc[h], 0.f) / (float)NL;
    __syncthreads();
    float s = ac_b[h];
    for (int k = 0; k < 64; k++) s += ac_w[h * 64 + k] * o[k];
    t[h] = o[h] + fmaxf(s, 0.f);
    __syncthreads();
    if (h < 10) {
        float l = fl_b[h];
        for (int k = 0; k < 64; k++) l += fl_w[h * 64 + k] * t[k];
        lg[h] = l;
    }
    __syncthreads();
    if (h < 10) {
        float m = -1e30f;
        for (int i = 0; i < 10; i++) m = fmaxf(m, lg[i]);
        float se = 0.f;
        for (int i = 0; i < 10; i++) se += expf(lg[i] - m);
        out[h] = lg[h] - m - logf(se);
    }
}

// ---------------- launch -----------------------------------------------------
extern "C" void kernel_launch(void* const* d_in, const int* in_sizes, int n_in,
                              void* d_out, int out_size) {
    const float* x     = (const float*)d_in[0];
    const int*   ei    = (const int*)  d_in[1];
    const float* np1_w = (const float*)d_in[2];
    const float* np1_b = (const float*)d_in[3];
    const float* np2_w = (const float*)d_in[4];
    const float* np3_w = (const float*)d_in[5];
    const float* c0m1w = (const float*)d_in[6];
    const float* c0m1b = (const float*)d_in[7];
    const float* c0m2w = (const float*)d_in[8];
    const float* c0m2b = (const float*)d_in[9];
    const float* c0m4w = (const float*)d_in[10];
    const float* c0m4b = (const float*)d_in[11];
    const float* cm1w  = (const float*)d_in[12];
    const float* cm1b  = (const float*)d_in[13];
    const float* cm2w  = (const float*)d_in[14];
    const float* cm2b  = (const float*)d_in[15];
    const float* cm4w  = (const float*)d_in[16];
    const float* cm4b  = (const float*)d_in[17];
    const float* bn_g  = (const float*)d_in[18];
    const float* bn_b  = (const float*)d_in[19];
    const float* fe1w  = (const float*)d_in[20];
    const float* fe1b  = (const float*)d_in[21];
    const float* fe2w  = (const float*)d_in[22];
    const float* fe3w  = (const float*)d_in[23];
    const float* ac_w  = (const float*)d_in[24];
    const float* ac_b  = (const float*)d_in[25];
    const float* fl_w  = (const float*)d_in[26];
    const float* fl_b  = (const float*)d_in[27];

    float *U, *V, *O1, *O2, *M, *ST, *AC;
    cudaGetSymbolAddress((void**)&U,  g_U);
    cudaGetSymbolAddress((void**)&V,  g_V);
    cudaGetSymbolAddress((void**)&O1, g_O1);
    cudaGetSymbolAddress((void**)&O2, g_O2);
    cudaGetSymbolAddress((void**)&M,  g_M);
    cudaGetSymbolAddress((void**)&ST, g_ST);
    cudaGetSymbolAddress((void**)&AC, g_AC);

    static bool attr_done = false;
    if (!attr_done) {
        cudaFuncSetAttribute(k_mix_mma, cudaFuncAttributeMaxDynamicSharedMemorySize,
                             (64 * 132 + 32 * 264) * sizeof(float));
        attr_done = true;
    }

    // Build adjacency tensor A (32 channels) in g_U
    k_zero<<<(32u * NP) / 256, 256>>>(U, AC);
    k_scatter<<<(EE * 32) / 256, 256>>>(x, ei, U);

    // no_prop extractor
    k_ext_stats<<<TWOF, 256>>>(U, ST);
    k_ext_combine<<<1, 64>>>(ST, np1_w, np1_b, np2_w, np3_w, TWOF, AC);

    const float* cur = U;
    float*       nxt = V;
    for (int l = 0; l < NL; l++) {
        const int Cin = l ? 64 : TWOF;
        const float* m1w = l ? cm1w + (l - 1) * 64 * 64  : c0m1w;
        const float* m1b = l ? cm1b + (l - 1) * 64       : c0m1b;
        const float* m2w = l ? cm2w + (l - 1) * 64 * 64  : c0m2w;
        const float* m2b = l ? cm2b + (l - 1) * 64       : c0m2b;
        const float* m4w = l ? cm4w + (l - 1) * 64 * 128 : c0m4w;
        const float* m4b = l ? cm4b + (l - 1) * 64       : c0m4b;

        size_t sh1 = (size_t)(64 * (Cin + 4) + 32 * 264) * sizeof(float);
        k_mix_mma<<<1024, 256, sh1>>>(cur, Cin, nullptr, 0, m1w, m1b, O1);
        k_mix_mma<<<1024, 256, sh1>>>(cur, Cin, nullptr, 0, m2w, m2b, O2);

        k_mma<<<dim3(4, 4, 64), 256>>>(O1, O2, M);

        size_t sh4 = (size_t)(64 * (64 + Cin + 4) + 32 * 264) * sizeof(float);
        k_mix_mma<<<1024, 256, sh4>>>(M, 64, cur, Cin, m4w, m4b, nxt);

        k_bn_stats<<<64, 256>>>(nxt, ST);
        k_bn_apply<<<(64u * NP) / 256, 256>>>(nxt, ST, bn_g + 64 * l, bn_b + 64 * l);

        k_ext_stats<<<64, 256>>>(nxt, ST);
        k_ext_combine<<<1, 64>>>(ST, fe1w + l * 64 * 64, fe1b + l * 64,
                                 fe2w + l * 64 * 64, fe3w + l * 64 * 64, 64, AC);

        float* tmp = (float*)cur; cur = nxt; nxt = tmp;
    }

    k_head<<<1, 64>>>(AC, ac_w, ac_b, fl_w, fl_b, (float*)d_out);
}

// round 4
// speedup vs baseline: 3.4643x; 1.2484x over previous
#include <cuda_runtime.h>
#include <math.h>
#include <stdint.h>

#define NN   512
#define NP   (NN*NN)        // 262144
#define FIN  16
#define TWOF 32
#define EE   16384
#define NL   3

// g_ST layout
#define ST_SUM   0
#define ST_SQ    64
#define ST_TR    128
#define ST_S     192
#define ST_T     256
#define ST_ATR   320
#define ST_ATOT  384

// ---------------- scratch (device globals; no allocation allowed) ----------
__device__ float g_U [64u*NP];
__device__ float g_V [64u*NP];
__device__ float g_O1[64u*NP];
__device__ float g_O2[64u*NP];
__device__ float g_M [64u*NP];
__device__ float g_ST[448];
__device__ float g_AC[64];

#define MMA_TF32(d, a, b)                                                      \
    asm volatile(                                                              \
        "mma.sync.aligned.m16n8k8.row.col.f32.tf32.tf32.f32 "                  \
        "{%0,%1,%2,%3},{%4,%5,%6,%7},{%8,%9},{%0,%1,%2,%3};"                   \
        : "+f"(d[0]), "+f"(d[1]), "+f"(d[2]), "+f"(d[3])                       \
        : "r"(a[0]), "r"(a[1]), "r"(a[2]), "r"(a[3]), "r"(b[0]), "r"(b[1]))

__device__ __forceinline__ void cp16(float* smem, const float* g) {
    uint32_t a = (uint32_t)__cvta_generic_to_shared(smem);
    asm volatile("cp.async.cg.shared.global [%0], [%1], 16;" :: "r"(a), "l"(g));
}

// ---------------- init ------------------------------------------------------
__global__ void k_zero(float* U, float* AC, float* ST) {
    int i = blockIdx.x * 256 + threadIdx.x;           // 32*NP threads
    U[i] = 0.f;
    if (i < 64)  AC[i] = 0.f;
    if (i < 448) ST[i] = 0.f;
}

// ---------------- scatter edges into A[c][src][dst] -------------------------
__global__ void k_scatter(const float* __restrict__ x, const int* __restrict__ ei,
                          float* __restrict__ A) {
    int t = blockIdx.x * 256 + threadIdx.x;           // EE*32 threads
    int e = t >> 5, c = t & 31;
    int s = ei[e], d = ei[EE + e];
    float v = (c < FIN) ? x[s * FIN + c] : x[d * FIN + (c - FIN)];
    atomicAdd(&A[(size_t)c * NP + s * NN + d], v);
}

// ---------------- per-channel trace + total (A only) ------------------------
__global__ void k_ext_stats(const float* __restrict__ U, float* __restrict__ st) {
    int c = blockIdx.x;
    const float* u = U + (size_t)c * NP;
    float tot = 0.f, tr = 0.f;
    for (int i = threadIdx.x; i < NP;  i += 256) tot += u[i];
    for (int i = threadIdx.x; i < NN;  i += 256) tr  += u[i * (NN + 1)];
    __shared__ float s1[256], s2[256];
    s1[threadIdx.x] = tot; s2[threadIdx.x] = tr; __syncthreads();
    for (int o = 128; o > 0; o >>= 1) {
        if (threadIdx.x < o) { s1[threadIdx.x] += s1[threadIdx.x+o]; s2[threadIdx.x] += s2[threadIdx.x+o]; }
        __syncthreads();
    }
    if (threadIdx.x == 0) { st[c] = s2[0]; st[64 + c] = s1[0]; }
}

// ---------------- extractor combine for A (tiny) -----------------------------
__global__ void k_ext_combine(const float* __restrict__ st,
                              const float* __restrict__ w1, const float* __restrict__ b1,
                              const float* __restrict__ w2, const float* __restrict__ w3,
                              int C, float* __restrict__ acc) {
    int h = threadIdx.x;                               // 64 threads
    __shared__ float osh[64];
    float o = b1[h];
    for (int c = 0; c < C; c++) {
        float tr = st[c];
        float s  = (st[64 + c] - tr) / (512.f * 511.f);
        o += w1[h * C + c] * (tr / 512.f) + w2[h * C + c] * s;
    }
    osh[h] = o; __syncthreads();
    float a = o;
    for (int k = 0; k < 64; k++) a += w3[h * 64 + k] * fmaxf(osh[k], 0.f);
    acc[h] += a;
}

// ---------------- fused mix1+mix2 (shared input tile, BN folded) -------------
// O1/O2[64][NP] = (W·diag(s)) @ in[Ct][NP] + (b + W·t)
__global__ __launch_bounds__(256) void k_mixAB(
    const float* __restrict__ in, int Ct,
    const float* __restrict__ W1, const float* __restrict__ b1,
    const float* __restrict__ W2, const float* __restrict__ b2,
    const float* __restrict__ ST, int fold,
    float* __restrict__ O1, float* __restrict__ O2) {
    const int ld2 = Ct + 4;
    extern __shared__ float sh[];
    float* Ws1 = sh;
    float* Ws2 = Ws1 + 64 * ld2;
    float* bs1 = Ws2 + 64 * ld2;
    float* bs2 = bs1 + 64;
    float* Us  = bs2 + 64;          // [32][136]

    for (int i = threadIdx.x; i < 64 * Ct; i += 256) {
        int o = i / Ct, c = i - o * Ct;
        float s = fold ? ST[ST_S + c] : 1.f;
        Ws1[o * ld2 + c] = W1[i] * s;
        Ws2[o * ld2 + c] = W2[i] * s;
    }
    if (threadIdx.x < 64) {
        int o = threadIdx.x;
        float a1 = b1[o], a2 = b2[o];
        if (fold)
            for (int c = 0; c < Ct; c++) {
                float t = ST[ST_T + c];
                a1 += W1[o * Ct + c] * t;
                a2 += W2[o * Ct + c] * t;
            }
        bs1[o] = a1; bs2[o] = a2;
    }

    const int p0   = blockIdx.x * 128;
    const int lane = threadIdx.x & 31;
    const int wid  = threadIdx.x >> 5;
    const int cg = wid & 3, rg = wid >> 2;
    const int lq = lane & 3, lr = lane >> 2;

    float acc1[2][4][4], acc2[2][4][4];
#pragma unroll
    for (int mi = 0; mi < 2; mi++)
#pragma unroll
        for (int nj = 0; nj < 4; nj++)
#pragma unroll
            for (int q = 0; q < 4; q++) { acc1[mi][nj][q] = 0.f; acc2[mi][nj][q] = 0.f; }

    for (int k0 = 0; k0 < Ct; k0 += 32) {
        __syncthreads();
        for (int i = threadIdx.x; i < 1024; i += 256) {       // 32x128 floats
            int kk = i >> 5, c4 = (i & 31) << 2;
            float4 v = *(const float4*)(in + (size_t)(k0 + kk) * NP + p0 + c4);
            *(float4*)(Us + kk * 136 + c4) = v;
        }
        __syncthreads();
#pragma unroll
        for (int kk = 0; kk < 32; kk += 8) {
            uint32_t a1[2][4], a2[2][4], b[4][2];
#pragma unroll
            for (int mi = 0; mi < 2; mi++) {
                int r = rg * 32 + mi * 16 + lr;
                int kc = k0 + kk + lq;
                a1[mi][0] = __float_as_uint(Ws1[r * ld2 + kc]);
                a1[mi][1] = __float_as_uint(Ws1[(r + 8) * ld2 + kc]);
                a1[mi][2] = __float_as_uint(Ws1[r * ld2 + kc + 4]);
                a1[mi][3] = __float_as_uint(Ws1[(r + 8) * ld2 + kc + 4]);
                a2[mi][0] = __float_as_uint(Ws2[r * ld2 + kc]);
                a2[mi][1] = __float_as_uint(Ws2[(r + 8) * ld2 + kc]);
                a2[mi][2] = __float_as_uint(Ws2[r * ld2 + kc + 4]);
                a2[mi][3] = __float_as_uint(Ws2[(r + 8) * ld2 + kc + 4]);
            }
#pragma unroll
            for (int nj = 0; nj < 4; nj++) {
                int c = cg * 32 + nj * 8 + lr;
                b[nj][0] = __float_as_uint(Us[(kk + lq) * 136 + c]);
                b[nj][1] = __float_as_uint(Us[(kk + 4 + lq) * 136 + c]);
            }
#pragma unroll
            for (int mi = 0; mi < 2; mi++)
#pragma unroll
                for (int nj = 0; nj < 4; nj++) {
                    MMA_TF32(acc1[mi][nj], a1[mi], b[nj]);
                    MMA_TF32(acc2[mi][nj], a2[mi], b[nj]);
                }
        }
    }

#pragma unroll
    for (int mi = 0; mi < 2; mi++) {
        int o0 = rg * 32 + mi * 16 + lr, o1 = o0 + 8;
        float c10 = bs1[o0], c11 = bs1[o1], c20 = bs2[o0], c21 = bs2[o1];
#pragma unroll
        for (int nj = 0; nj < 4; nj++) {
            int col = p0 + cg * 32 + nj * 8 + 2 * lq;
            *(float2*)(O1 + (size_t)o0 * NP + col) = make_float2(acc1[mi][nj][0] + c10, acc1[mi][nj][1] + c10);
            *(float2*)(O1 + (size_t)o1 * NP + col) = make_float2(acc1[mi][nj][2] + c11, acc1[mi][nj][3] + c11);
            *(float2*)(O2 + (size_t)o0 * NP + col) = make_float2(acc2[mi][nj][0] + c20, acc2[mi][nj][1] + c20);
            *(float2*)(O2 + (size_t)o1 * NP + col) = make_float2(acc2[mi][nj][2] + c21, acc2[mi][nj][3] + c21);
        }
    }
}

// ---------------- mix4: concat(M, cur) -> out, with stats epilogue -----------
__global__ __launch_bounds__(256) void k_mix4(
    const float* __restrict__ Mt, const float* __restrict__ cur, int C2,
    const float* __restrict__ W, const float* __restrict__ bias,
    int fold, float* __restrict__ out, float* __restrict__ ST) {
    const int Ct = 64 + C2;
    const int ld2 = Ct + 4;
    extern __shared__ float sh[];
    float* Ws = sh;                  // 64*ld2
    float* bs = Ws + 64 * ld2;       // 64
    float* Us = bs + 64;             // 32*136
    float* sSum = Us + 32 * 136;     // 64
    float* sSq  = sSum + 64;         // 64
    float* sTr  = sSq + 64;          // 64

    for (int i = threadIdx.x; i < 64 * Ct; i += 256) {
        int o = i / Ct, c = i - o * Ct;
        float s = (c >= 64 && fold) ? ST[ST_S + c - 64] : 1.f;
        Ws[o * ld2 + c] = W[i] * s;
    }
    if (threadIdx.x < 64) {
        int o = threadIdx.x;
        float a = bias[o];
        if (fold)
            for (int c = 64; c < Ct; c++) a += W[o * Ct + c] * ST[ST_T + c - 64];
        bs[o] = a;
    }
    if (threadIdx.x < 192) sSum[threadIdx.x] = 0.f;   // zeros sum/sq/tr

    const int p0   = blockIdx.x * 128;
    const int lane = threadIdx.x & 31;
    const int wid  = threadIdx.x >> 5;
    const int cg = wid & 3, rg = wid >> 2;
    const int lq = lane & 3, lr = lane >> 2;

    float acc[2][4][4];
#pragma unroll
    for (int mi = 0; mi < 2; mi++)
#pragma unroll
        for (int nj = 0; nj < 4; nj++)
#pragma unroll
            for (int q = 0; q < 4; q++) acc[mi][nj][q] = 0.f;

    for (int k0 = 0; k0 < Ct; k0 += 32) {
        __syncthreads();
        for (int i = threadIdx.x; i < 1024; i += 256) {
            int kk = i >> 5, c4 = (i & 31) << 2;
            int c = k0 + kk;
            const float* src = (c < 64) ? Mt + (size_t)c * NP
                                        : cur + (size_t)(c - 64) * NP;
            *(float4*)(Us + kk * 136 + c4) = *(const float4*)(src + p0 + c4);
        }
        __syncthreads();
#pragma unroll
        for (int kk = 0; kk < 32; kk += 8) {
            uint32_t a[2][4], b[4][2];
#pragma unroll
            for (int mi = 0; mi < 2; mi++) {
                int r = rg * 32 + mi * 16 + lr;
                int kc = k0 + kk + lq;
                a[mi][0] = __float_as_uint(Ws[r * ld2 + kc]);
                a[mi][1] = __float_as_uint(Ws[(r + 8) * ld2 + kc]);
                a[mi][2] = __float_as_uint(Ws[r * ld2 + kc + 4]);
                a[mi][3] = __float_as_uint(Ws[(r + 8) * ld2 + kc + 4]);
            }
#pragma unroll
            for (int nj = 0; nj < 4; nj++) {
                int c = cg * 32 + nj * 8 + lr;
                b[nj][0] = __float_as_uint(Us[(kk + lq) * 136 + c]);
                b[nj][1] = __float_as_uint(Us[(kk + 4 + lq) * 136 + c]);
            }
#pragma unroll
            for (int mi = 0; mi < 2; mi++)
#pragma unroll
                for (int nj = 0; nj < 4; nj++) MMA_TF32(acc[mi][nj], a[mi], b[nj]);
        }
    }
    __syncthreads();    // sSum zeros + Ws use complete before stats accumulate

    // diagonal column inside this block (at most one)
    int dp = ((p0 + 512) / 513) * 513;
    bool hasDiag = (dp < p0 + 128);

#pragma unroll
    for (int mi = 0; mi < 2; mi++) {
        int o0 = rg * 32 + mi * 16 + lr, o1 = o0 + 8;
        float b0 = bs[o0], b1v = bs[o1];
        float s0 = 0.f, q0 = 0.f, s1 = 0.f, q1 = 0.f;
#pragma unroll
        for (int nj = 0; nj < 4; nj++) {
            int col = p0 + cg * 32 + nj * 8 + 2 * lq;
            float v00 = acc[mi][nj][0] + b0, v01 = acc[mi][nj][1] + b0;
            float v10 = acc[mi][nj][2] + b1v, v11 = acc[mi][nj][3] + b1v;
            if (out) {
                *(float2*)(out + (size_t)o0 * NP + col) = make_float2(v00, v01);
                *(float2*)(out + (size_t)o1 * NP + col) = make_float2(v10, v11);
            }
            s0 += v00 + v01; q0 += v00 * v00 + v01 * v01;
            s1 += v10 + v11; q1 += v10 * v10 + v11 * v11;
            if (hasDiag) {
                if (col == dp)     { atomicAdd(&sTr[o0], v00); atomicAdd(&sTr[o1], v10); }
                if (col + 1 == dp) { atomicAdd(&sTr[o0], v01); atomicAdd(&sTr[o1], v11); }
            }
        }
        // reduce over lq (4 lanes share the same channel rows)
#pragma unroll
        for (int off = 1; off < 4; off <<= 1) {
            s0 += __shfl_xor_sync(0xffffffffu, s0, off);
            q0 += __shfl_xor_sync(0xffffffffu, q0, off);
            s1 += __shfl_xor_sync(0xffffffffu, s1, off);
            q1 += __shfl_xor_sync(0xffffffffu, q1, off);
        }
        if (lq == 0) {
            atomicAdd(&sSum[o0], s0); atomicAdd(&sSq[o0], q0);
            atomicAdd(&sSum[o1], s1); atomicAdd(&sSq[o1], q1);
        }
    }
    __syncthreads();
    if (threadIdx.x < 64) {
        int c = threadIdx.x;
        atomicAdd(&ST[ST_SUM + c], sSum[c]);
        atomicAdd(&ST[ST_SQ  + c], sSq[c]);
        if (sTr[c] != 0.f) atomicAdd(&ST[ST_TR + c], sTr[c]);
    }
}

// ---------------- batched 512^3 tf32 GEMM, cp.async double-buffered ----------
__global__ __launch_bounds__(256) void k_mma(const float* __restrict__ A,
                                             const float* __restrict__ B,
                                             float* __restrict__ C) {
    extern __shared__ float dsm[];                 // 2 stages x (128*36 + 32*136)
    const int ch = blockIdx.z;
    const float* Ab = A + (size_t)ch * NP;
    const float* Bb = B + (size_t)ch * NP;
    float*       Cb = C + (size_t)ch * NP;
    const int tid  = threadIdx.x;
    const int lane = tid & 31, wid = tid >> 5;
    const int wr = wid >> 1, wc = wid & 1;
    const int lq = lane & 3, lr = lane >> 2;
    const int rowBase = blockIdx.y * 128;
    const int colBase = blockIdx.x * 128;

    float acc[2][8][4];
#pragma unroll
    for (int mi = 0; mi < 2; mi++)
#pragma unroll
        for (int nj = 0; nj < 8; nj++)
#pragma unroll
            for (int q = 0; q < 4; q++) acc[mi][nj][q] = 0.f;

    auto loadTile = [&](int k0, int st) {
        float* As = dsm + st * 8960;
        float* Bs = As + 4608;
#pragma unroll
        for (int i = 0; i < 4; i++) {
            int lin = tid + i * 256;
            int r = lin >> 3, k4 = (lin & 7) << 2;
            cp16(As + r * 36 + k4, Ab + (size_t)(rowBase + r) * NN + k0 + k4);
        }
#pragma unroll
        for (int i = 0; i < 4; i++) {
            int lin = tid + i * 256;
            int kk = lin >> 5, c4 = (lin & 31) << 2;
            cp16(Bs + kk * 136 + c4, Bb + (size_t)(k0 + kk) * NN + colBase + c4);
        }
        asm volatile("cp.async.commit_group;");
    };

    loadTile(0, 0);
    for (int t = 0; t < 16; t++) {
        if (t < 15) {
            loadTile((t + 1) * 32, (t + 1) & 1);
            asm volatile("cp.async.wait_group 1;");
        } else {
            asm volatile("cp.async.wait_group 0;");
        }
        __syncthreads();
        const float* As = dsm + (t & 1) * 8960;
        const float* Bs = As + 4608;
#pragma unroll
        for (int kk = 0; kk < 32; kk += 8) {
            uint32_t a[2][4], b[8][2];
#pragma unroll
            for (int mi = 0; mi < 2; mi++) {
                int r = wr * 32 + mi * 16 + lr;
                a[mi][0] = __float_as_uint(As[r * 36 + kk + lq]);
                a[mi][1] = __float_as_uint(As[(r + 8) * 36 + kk + lq]);
                a[mi][2] = __float_as_uint(As[r * 36 + kk + 4 + lq]);
                a[mi][3] = __float_as_uint(As[(r + 8) * 36 + kk + 4 + lq]);
            }
#pragma unroll
            for (int nj = 0; nj < 8; nj++) {
                int c = wc * 64 + nj * 8 + lr;
                b[nj][0] = __float_as_uint(Bs[(kk + lq) * 136 + c]);
                b[nj][1] = __float_as_uint(Bs[(kk + 4 + lq) * 136 + c]);
            }
#pragma unroll
            for (int mi = 0; mi < 2; mi++)
#pragma unroll
                for (int nj = 0; nj < 8; nj++) MMA_TF32(acc[mi][nj], a[mi], b[nj]);
        }
        __syncthreads();
    }

#pragma unroll
    for (int mi = 0; mi < 2; mi++) {
        int r0 = rowBase + wr * 32 + mi * 16 + lr;
#pragma unroll
        for (int nj = 0; nj < 8; nj++) {
            int col = colBase + wc * 64 + nj * 8 + 2 * lq;
            *(float2*)(Cb + (size_t)r0 * NN + col) =
                make_float2(acc[mi][nj][0], acc[mi][nj][1]);
            *(float2*)(Cb + (size_t)(r0 + 8) * NN + col) =
                make_float2(acc[mi][nj][2], acc[mi][nj][3]);
        }
    }
}

// ---------------- finalize: BN params + analytic extractor -------------------
__global__ void k_finalize(float* __restrict__ ST,
                           const float* __restrict__ g, const float* __restrict__ b,
                           const float* __restrict__ w1, const float* __restrict__ b1,
                           const float* __restrict__ w2, const float* __restrict__ w3,
                           float* __restrict__ acc) {
    int h = threadIdx.x;                               // 64 threads
    __shared__ float str[64], stot[64], osh[64];
    float sum = ST[ST_SUM + h], sq = ST[ST_SQ + h], tr = ST[ST_TR + h];
    float m   = sum / (float)NP;
    float var = sq / (float)NP - m * m;
    float s   = g[h] * rsqrtf(var + 1e-5f);
    float t   = b[h] - m * s;
    ST[ST_S + h] = s; ST[ST_T + h] = t;
    ST[ST_SUM + h] = 0.f; ST[ST_SQ + h] = 0.f; ST[ST_TR + h] = 0.f;
    str[h]  = tr * s + 512.f * t;
    stot[h] = sum * s + (float)NP * t;
    __syncthreads();
    float o = b1[h];
    for (int c = 0; c < 64; c++) {
        float trc = str[c];
        float sc  = (stot[c] - trc) / (512.f * 511.f);
        o += w1[h * 64 + c] * (trc / 512.f) + w2[h * 64 + c] * sc;
    }
    osh[h] = o; __syncthreads();
    float a = o;
    for (int k = 0; k < 64; k++) a += w3[h * 64 + k] * fmaxf(osh[k], 0.f);
    acc[h] += a;
}

// ---------------- head -------------------------------------------------------
__global__ void k_head(const float* __restrict__ acc,
                       const float* __restrict__ ac_w, const float* __restrict__ ac_b,
                       const float* __restrict__ fl_w, const float* __restrict__ fl_b,
                       float* __restrict__ out) {
    __shared__ float o[64], t[64], lg[10];
    int h = threadIdx.x;
    o[h] = fmaxf(acc[h], 0.f) / (float)NL;
    __syncthreads();
    float s = ac_b[h];
    for (int k = 0; k < 64; k++) s += ac_w[h * 64 + k] * o[k];
    t[h] = o[h] + fmaxf(s, 0.f);
    __syncthreads();
    if (h < 10) {
        float l = fl_b[h];
        for (int k = 0; k < 64; k++) l += fl_w[h * 64 + k] * t[k];
        lg[h] = l;
    }
    __syncthreads();
    if (h < 10) {
        float m = -1e30f;
        for (int i = 0; i < 10; i++) m = fmaxf(m, lg[i]);
        float se = 0.f;
        for (int i = 0; i < 10; i++) se += expf(lg[i] - m);
        out[h] = lg[h] - m - logf(se);
    }
}

// ---------------- launch -----------------------------------------------------
extern "C" void kernel_launch(void* const* d_in, const int* in_sizes, int n_in,
                              void* d_out, int out_size) {
    const float* x     = (const float*)d_in[0];
    const int*   ei    = (const int*)  d_in[1];
    const float* np1_w = (const float*)d_in[2];
    const float* np1_b = (const float*)d_in[3];
    const float* np2_w = (const float*)d_in[4];
    const float* np3_w = (const float*)d_in[5];
    const float* c0m1w = (const float*)d_in[6];
    const float* c0m1b = (const float*)d_in[7];
    const float* c0m2w = (const float*)d_in[8];
    const float* c0m2b = (const float*)d_in[9];
    const float* c0m4w = (const float*)d_in[10];
    const float* c0m4b = (const float*)d_in[11];
    const float* cm1w  = (const float*)d_in[12];
    const float* cm1b  = (const float*)d_in[13];
    const float* cm2w  = (const float*)d_in[14];
    const float* cm2b  = (const float*)d_in[15];
    const float* cm4w  = (const float*)d_in[16];
    const float* cm4b  = (const float*)d_in[17];
    const float* bn_g  = (const float*)d_in[18];
    const float* bn_b  = (const float*)d_in[19];
    const float* fe1w  = (const float*)d_in[20];
    const float* fe1b  = (const float*)d_in[21];
    const float* fe2w  = (const float*)d_in[22];
    const float* fe3w  = (const float*)d_in[23];
    const float* ac_w  = (const float*)d_in[24];
    const float* ac_b  = (const float*)d_in[25];
    const float* fl_w  = (const float*)d_in[26];
    const float* fl_b  = (const float*)d_in[27];

    float *U, *V, *O1, *O2, *M, *ST, *AC;
    cudaGetSymbolAddress((void**)&U,  g_U);
    cudaGetSymbolAddress((void**)&V,  g_V);
    cudaGetSymbolAddress((void**)&O1, g_O1);
    cudaGetSymbolAddress((void**)&O2, g_O2);
    cudaGetSymbolAddress((void**)&M,  g_M);
    cudaGetSymbolAddress((void**)&ST, g_ST);
    cudaGetSymbolAddress((void**)&AC, g_AC);

    static bool attr_done = false;
    if (!attr_done) {
        cudaFuncSetAttribute(k_mma,   cudaFuncAttributeMaxDynamicSharedMemorySize, 2 * 8960 * 4);
        cudaFuncSetAttribute(k_mixAB, cudaFuncAttributeMaxDynamicSharedMemorySize, 80 * 1024);
        cudaFuncSetAttribute(k_mix4,  cudaFuncAttributeMaxDynamicSharedMemorySize, 80 * 1024);
        attr_done = true;
    }

    k_zero<<<(32u * NP) / 256, 256>>>(U, AC, ST);
    k_scatter<<<(EE * 32) / 256, 256>>>(x, ei, U);

    k_ext_stats<<<TWOF, 256>>>(U, ST + ST_ATR);
    k_ext_combine<<<1, 64>>>(ST + ST_ATR, np1_w, np1_b, np2_w, np3_w, TWOF, AC);

    const float* cur = U;
    float*       nxt = V;
    for (int l = 0; l < NL; l++) {
        const int Cin = l ? 64 : TWOF;
        const int fold = (l > 0) ? 1 : 0;
        const float* m1w = l ? cm1w + (l - 1) * 64 * 64  : c0m1w;
        const float* m1b = l ? cm1b + (l - 1) * 64       : c0m1b;
        const float* m2w = l ? cm2w + (l - 1) * 64 * 64  : c0m2w;
        const float* m2b = l ? cm2b + (l - 1) * 64       : c0m2b;
        const float* m4w = l ? cm4w + (l - 1) * 64 * 128 : c0m4w;
        const float* m4b = l ? cm4b + (l - 1) * 64       : c0m4b;

        size_t shAB = (size_t)(2 * 64 * (Cin + 4) + 128 + 32 * 136) * sizeof(float);
        k_mixAB<<<2048, 256, shAB>>>(cur, Cin, m1w, m1b, m2w, m2b, ST, fold, O1, O2);

        k_mma<<<dim3(4, 4, 64), 256, 2 * 8960 * 4>>>(O1, O2, M);

        size_t sh4 = (size_t)(64 * (64 + Cin + 4) + 64 + 32 * 136 + 192) * sizeof(float);
        k_mix4<<<2048, 256, sh4>>>(M, cur, Cin, m4w, m4b, fold,
                                   (l < NL - 1) ? nxt : nullptr, ST);

        k_finalize<<<1, 64>>>(ST, bn_g + 64 * l, bn_b + 64 * l,
                              fe1w + l * 64 * 64, fe1b + l * 64,
                              fe2w + l * 64 * 64, fe3w + l * 64 * 64, AC);

        float* tmp = (float*)cur; cur = nxt; nxt = tmp;
    }

    k_head<<<1, 64>>>(AC, ac_w, ac_b, fl_w, fl_b, (float*)d_out);
}

// round 5
// speedup vs baseline: 4.4327x; 1.2795x over previous
#include <cuda_runtime.h>
#include <cuda_bf16.h>
#include <math.h>
#include <stdint.h>

#define NN   512
#define NP   (NN*NN)        // 262144
#define FIN  16
#define TWOF 32
#define EE   16384
#define NL   3

// g_ST layout
#define ST_SUM   0
#define ST_SQ    64
#define ST_TR    128
#define ST_S     192
#define ST_T     256
#define ST_ATR   320

typedef __nv_bfloat16 bf16;
typedef __nv_bfloat162 bf162;

// ---------------- scratch (device globals; no allocation allowed) ----------
__device__ float g_U [32u*NP];        // fp32 adjacency (scatter target)
__device__ bf16  g_Ub[32u*NP];        // bf16 adjacency
__device__ bf16  g_V0[64u*NP];
__device__ bf16  g_V1[64u*NP];
__device__ bf16  g_O1[64u*NP];
__device__ bf16  g_O2[64u*NP];
__device__ bf16  g_M [64u*NP];
__device__ float g_ST[448];
__device__ float g_AC[64];

#define MMA_BF16(d, a, b)                                                      \
    asm volatile(                                                              \
        "mma.sync.aligned.m16n8k16.row.col.f32.bf16.bf16.f32 "                 \
        "{%0,%1,%2,%3},{%4,%5,%6,%7},{%8,%9},{%0,%1,%2,%3};"                   \
        : "+f"(d[0]), "+f"(d[1]), "+f"(d[2]), "+f"(d[3])                       \
        : "r"(a[0]), "r"(a[1]), "r"(a[2]), "r"(a[3]), "r"(b[0]), "r"(b[1]))

#define LDSM4(R, addr)                                                         \
    asm volatile("ldmatrix.sync.aligned.m8n8.x4.shared.b16 {%0,%1,%2,%3},[%4];"\
        : "=r"(R[0]), "=r"(R[1]), "=r"(R[2]), "=r"(R[3]) : "r"(addr))

#define LDSM4T(R, addr)                                                        \
    asm volatile("ldmatrix.sync.aligned.m8n8.x4.trans.shared.b16 {%0,%1,%2,%3},[%4];"\
        : "=r"(R[0]), "=r"(R[1]), "=r"(R[2]), "=r"(R[3]) : "r"(addr))

__device__ __forceinline__ uint32_t smaddr(const void* p) {
    return (uint32_t)__cvta_generic_to_shared(p);
}
__device__ __forceinline__ void cp16(void* smem, const void* g) {
    asm volatile("cp.async.cg.shared.global [%0], [%1], 16;"
                 :: "r"(smaddr(smem)), "l"(g));
}

// ---------------- init ------------------------------------------------------
__global__ void k_zero(float* U, float* AC, float* ST) {
    int i = blockIdx.x * 256 + threadIdx.x;           // 32*NP threads
    U[i] = 0.f;
    if (i < 64)  AC[i] = 0.f;
    if (i < 448) ST[i] = 0.f;
}

// ---------------- scatter edges into A[c][src][dst] -------------------------
__global__ void k_scatter(const float* __restrict__ x, const int* __restrict__ ei,
                          float* __restrict__ A) {
    int t = blockIdx.x * 256 + threadIdx.x;           // EE*32 threads
    int e = t >> 5, c = t & 31;
    int s = ei[e], d = ei[EE + e];
    float v = (c < FIN) ? x[s * FIN + c] : x[d * FIN + (c - FIN)];
    atomicAdd(&A[(size_t)c * NP + s * NN + d], v);
}

// ---------------- per-channel trace + total (A), and fp32->bf16 convert ------
__global__ void k_ext_stats(const float* __restrict__ U, float* __restrict__ st,
                            bf16* __restrict__ Ub) {
    int c = blockIdx.x;
    const float* u = U + (size_t)c * NP;
    bf16* ub = Ub + (size_t)c * NP;
    float tot = 0.f, tr = 0.f;
    for (int i = threadIdx.x; i < NP;  i += 256) {
        float v = u[i];
        tot += v;
        ub[i] = __float2bfloat16_rn(v);
    }
    for (int i = threadIdx.x; i < NN;  i += 256) tr  += u[i * (NN + 1)];
    __shared__ float s1[256], s2[256];
    s1[threadIdx.x] = tot; s2[threadIdx.x] = tr; __syncthreads();
    for (int o = 128; o > 0; o >>= 1) {
        if (threadIdx.x < o) { s1[threadIdx.x] += s1[threadIdx.x+o]; s2[threadIdx.x] += s2[threadIdx.x+o]; }
        __syncthreads();
    }
    if (threadIdx.x == 0) { st[c] = s2[0]; st[64 + c] = s1[0]; }
}

// ---------------- extractor combine for A (tiny) -----------------------------
__global__ void k_ext_combine(const float* __restrict__ st,
                              const float* __restrict__ w1, const float* __restrict__ b1,
                              const float* __restrict__ w2, const float* __restrict__ w3,
                              int C, float* __restrict__ acc) {
    int h = threadIdx.x;                               // 64 threads
    __shared__ float osh[64];
    float o = b1[h];
    for (int c = 0; c < C; c++) {
        float tr = st[c];
        float s  = (st[64 + c] - tr) / (512.f * 511.f);
        o += w1[h * C + c] * (tr / 512.f) + w2[h * C + c] * s;
    }
    osh[h] = o; __syncthreads();
    float a = o;
    for (int k = 0; k < 64; k++) a += w3[h * 64 + k] * fmaxf(osh[k], 0.f);
    acc[h] += a;
}

// ---------------- fused mix1+mix2, bf16 mma (BN folded) ----------------------
// O1/O2[64][NP] = (W·diag(s)) @ in[Ct][NP] + (b + W·t)
__global__ __launch_bounds__(256) void k_mixAB(
    const bf16* __restrict__ in, int Ct,
    const float* __restrict__ W1, const float* __restrict__ b1,
    const float* __restrict__ W2, const float* __restrict__ b2,
    const float* __restrict__ ST, int fold,
    bf16* __restrict__ O1, bf16* __restrict__ O2) {
    const int ld2 = Ct + 8;                 // row stride: (Ct+8)*2B = 16*odd
    extern __shared__ char shraw[];
    bf16*  Ws1 = (bf16*)shraw;              // [64][ld2]
    bf16*  Ws2 = Ws1 + 64 * ld2;
    float* bs1 = (float*)(Ws2 + 64 * ld2);
    float* bs2 = bs1 + 64;
    bf16*  Us  = (bf16*)(bs2 + 64);         // [32][136]

    for (int i = threadIdx.x; i < 64 * Ct; i += 256) {
        int o = i / Ct, c = i - o * Ct;
        float s = fold ? ST[ST_S + c] : 1.f;
        Ws1[o * ld2 + c] = __float2bfloat16_rn(W1[i] * s);
        Ws2[o * ld2 + c] = __float2bfloat16_rn(W2[i] * s);
    }
    if (threadIdx.x < 64) {
        int o = threadIdx.x;
        float a1 = b1[o], a2 = b2[o];
        if (fold)
            for (int c = 0; c < Ct; c++) {
                float t = ST[ST_T + c];
                a1 += W1[o * Ct + c] * t;
                a2 += W2[o * Ct + c] * t;
            }
        bs1[o] = a1; bs2[o] = a2;
    }

    const int p0   = blockIdx.x * 128;
    const int lane = threadIdx.x & 31;
    const int wid  = threadIdx.x >> 5;
    const int cg = wid & 3, rg = wid >> 2;
    const int lq = lane & 3, lr = lane >> 2;
    const int lml = lane & 15, lmh = (lane >> 4) << 3;

    float acc1[2][4][4], acc2[2][4][4];
#pragma unroll
    for (int mi = 0; mi < 2; mi++)
#pragma unroll
        for (int nj = 0; nj < 4; nj++)
#pragma unroll
            for (int q = 0; q < 4; q++) { acc1[mi][nj][q] = 0.f; acc2[mi][nj][q] = 0.f; }

    for (int k0 = 0; k0 < Ct; k0 += 32) {
        __syncthreads();
        for (int i = threadIdx.x; i < 512; i += 256) {        // 32 rows x 128 bf16
            int kk = i >> 4, c8 = (i & 15) << 3;
            *(float4*)(Us + kk * 136 + c8) =
                *(const float4*)(in + (size_t)(k0 + kk) * NP + p0 + c8);
        }
        __syncthreads();
#pragma unroll
        for (int kk = 0; kk < 32; kk += 16) {
            uint32_t a1[2][4], a2[2][4], bq[2][4];
#pragma unroll
            for (int mi = 0; mi < 2; mi++) {
                int r = rg * 32 + mi * 16 + lml;
                LDSM4(a1[mi], smaddr(Ws1 + r * ld2 + k0 + kk + lmh));
                LDSM4(a2[mi], smaddr(Ws2 + r * ld2 + k0 + kk + lmh));
            }
#pragma unroll
            for (int njp = 0; njp < 2; njp++)
                LDSM4T(bq[njp], smaddr(Us + (kk + lml) * 136 + cg * 32 + njp * 16 + lmh));
#pragma unroll
            for (int mi = 0; mi < 2; mi++)
#pragma unroll
                for (int njp = 0; njp < 2; njp++) {
                    MMA_BF16(acc1[mi][2*njp],   a1[mi], (bq[njp]));
                    MMA_BF16(acc1[mi][2*njp+1], a1[mi], (bq[njp]+2));
                    MMA_BF16(acc2[mi][2*njp],   a2[mi], (bq[njp]));
                    MMA_BF16(acc2[mi][2*njp+1], a2[mi], (bq[njp]+2));
                }
        }
    }

#pragma unroll
    for (int mi = 0; mi < 2; mi++) {
        int o0 = rg * 32 + mi * 16 + lr, o1 = o0 + 8;
        float c10 = bs1[o0], c11 = bs1[o1], c20 = bs2[o0], c21 = bs2[o1];
#pragma unroll
        for (int nj = 0; nj < 4; nj++) {
            int col = p0 + cg * 32 + nj * 8 + 2 * lq;
            *(bf162*)(O1 + (size_t)o0 * NP + col) =
                __floats2bfloat162_rn(acc1[mi][nj][0] + c10, acc1[mi][nj][1] + c10);
            *(bf162*)(O1 + (size_t)o1 * NP + col) =
                __floats2bfloat162_rn(acc1[mi][nj][2] + c11, acc1[mi][nj][3] + c11);
            *(bf162*)(O2 + (size_t)o0 * NP + col) =
                __floats2bfloat162_rn(acc2[mi][nj][0] + c20, acc2[mi][nj][1] + c20);
            *(bf162*)(O2 + (size_t)o1 * NP + col) =
                __floats2bfloat162_rn(acc2[mi][nj][2] + c21, acc2[mi][nj][3] + c21);
        }
    }
}

// ---------------- mix4: concat(M, cur) -> out (bf16), stats epilogue ---------
__global__ __launch_bounds__(256) void k_mix4(
    const bf16* __restrict__ Mt, const bf16* __restrict__ cur, int C2,
    const float* __restrict__ W, const float* __restrict__ bias,
    int fold, bf16* __restrict__ out, float* __restrict__ ST) {
    const int Ct = 64 + C2;
    const int ld2 = Ct + 8;
    extern __shared__ char shraw[];
    bf16*  Ws = (bf16*)shraw;               // [64][ld2]
    float* bs = (float*)(Ws + 64 * ld2);    // 64
    bf16*  Us = (bf16*)(bs + 64);           // [32][136]
    float* sSum = (float*)(Us + 32 * 136);  // 64
    float* sSq  = sSum + 64;                // 64
    float* sTr  = sSq + 64;                 // 64

    for (int i = threadIdx.x; i < 64 * Ct; i += 256) {
        int o = i / Ct, c = i - o * Ct;
        float s = (c >= 64 && fold) ? ST[ST_S + c - 64] : 1.f;
        Ws[o * ld2 + c] = __float2bfloat16_rn(W[i] * s);
    }
    if (threadIdx.x < 64) {
        int o = threadIdx.x;
        float a = bias[o];
        if (fold)
            for (int c = 64; c < Ct; c++) a += W[o * Ct + c] * ST[ST_T + c - 64];
        bs[o] = a;
    }
    if (threadIdx.x < 192) sSum[threadIdx.x] = 0.f;   // zeros sum/sq/tr

    const int p0   = blockIdx.x * 128;
    const int lane = threadIdx.x & 31;
    const int wid  = threadIdx.x >> 5;
    const int cg = wid & 3, rg = wid >> 2;
    const int lq = lane & 3, lr = lane >> 2;
    const int lml = lane & 15, lmh = (lane >> 4) << 3;

    float acc[2][4][4];
#pragma unroll
    for (int mi = 0; mi < 2; mi++)
#pragma unroll
        for (int nj = 0; nj < 4; nj++)
#pragma unroll
            for (int q = 0; q < 4; q++) acc[mi][nj][q] = 0.f;

    for (int k0 = 0; k0 < Ct; k0 += 32) {
        __syncthreads();
        for (int i = threadIdx.x; i < 512; i += 256) {
            int kk = i >> 4, c8 = (i & 15) << 3;
            int c = k0 + kk;
            const bf16* src = (c < 64) ? Mt + (size_t)c * NP
                                       : cur + (size_t)(c - 64) * NP;
            *(float4*)(Us + kk * 136 + c8) = *(const float4*)(src + p0 + c8);
        }
        __syncthreads();
#pragma unroll
        for (int kk = 0; kk < 32; kk += 16) {
            uint32_t a[2][4], bq[2][4];
#pragma unroll
            for (int mi = 0; mi < 2; mi++) {
                int r = rg * 32 + mi * 16 + lml;
                LDSM4(a[mi], smaddr(Ws + r * ld2 + k0 + kk + lmh));
            }
#pragma unroll
            for (int njp = 0; njp < 2; njp++)
                LDSM4T(bq[njp], smaddr(Us + (kk + lml) * 136 + cg * 32 + njp * 16 + lmh));
#pragma unroll
            for (int mi = 0; mi < 2; mi++)
#pragma unroll
                for (int njp = 0; njp < 2; njp++) {
                    MMA_BF16(acc[mi][2*njp],   a[mi], (bq[njp]));
                    MMA_BF16(acc[mi][2*njp+1], a[mi], (bq[njp]+2));
                }
        }
    }
    __syncthreads();

    int dp = ((p0 + 512) / 513) * 513;          // diagonal column inside block
    bool hasDiag = (dp < p0 + 128);

#pragma unroll
    for (int mi = 0; mi < 2; mi++) {
        int o0 = rg * 32 + mi * 16 + lr, o1 = o0 + 8;
        float b0 = bs[o0], b1v = bs[o1];
        float s0 = 0.f, q0 = 0.f, s1 = 0.f, q1 = 0.f;
#pragma unroll
        for (int nj = 0; nj < 4; nj++) {
            int col = p0 + cg * 32 + nj * 8 + 2 * lq;
            float v00 = acc[mi][nj][0] + b0, v01 = acc[mi][nj][1] + b0;
            float v10 = acc[mi][nj][2] + b1v, v11 = acc[mi][nj][3] + b1v;
            if (out) {
                *(bf162*)(out + (size_t)o0 * NP + col) = __floats2bfloat162_rn(v00, v01);
                *(bf162*)(out + (size_t)o1 * NP + col) = __floats2bfloat162_rn(v10, v11);
            }
            s0 += v00 + v01; q0 += v00 * v00 + v01 * v01;
            s1 += v10 + v11; q1 += v10 * v10 + v11 * v11;
            if (hasDiag) {
                if (col == dp)     { atomicAdd(&sTr[o0], v00); atomicAdd(&sTr[o1], v10); }
                if (col + 1 == dp) { atomicAdd(&sTr[o0], v01); atomicAdd(&sTr[o1], v11); }
            }
        }
#pragma unroll
        for (int off = 1; off < 4; off <<= 1) {
            s0 += __shfl_xor_sync(0xffffffffu, s0, off);
            q0 += __shfl_xor_sync(0xffffffffu, q0, off);
            s1 += __shfl_xor_sync(0xffffffffu, s1, off);
            q1 += __shfl_xor_sync(0xffffffffu, q1, off);
        }
        if (lq == 0) {
            atomicAdd(&sSum[o0], s0); atomicAdd(&sSq[o0], q0);
            atomicAdd(&sSum[o1], s1); atomicAdd(&sSq[o1], q1);
        }
    }
    __syncthreads();
    if (threadIdx.x < 64) {
        int c = threadIdx.x;
        atomicAdd(&ST[ST_SUM + c], sSum[c]);
        atomicAdd(&ST[ST_SQ  + c], sSq[c]);
        if (sTr[c] != 0.f) atomicAdd(&ST[ST_TR + c], sTr[c]);
    }
}

// ---------------- batched 512^3 bf16 GEMM, cp.async double-buffered ----------
#define LDA 72      // 144B row stride
#define LDB 136     // 272B row stride
#define STG (128*LDA + 64*LDB)   // bf16 elems per stage = 17920
__global__ __launch_bounds__(256) void k_mma(const bf16* __restrict__ A,
                                             const bf16* __restrict__ B,
                                             bf16* __restrict__ C) {
    extern __shared__ bf16 dsm[];                  // 2 stages
    const int ch = blockIdx.z;
    const bf16* Ab = A + (size_t)ch * NP;
    const bf16* Bb = B + (size_t)ch * NP;
    bf16*       Cb = C + (size_t)ch * NP;
    const int tid  = threadIdx.x;
    const int lane = tid & 31, wid = tid >> 5;
    const int wr = wid >> 1, wc = wid & 1;
    const int lq = lane & 3, lr = lane >> 2;
    const int lml = lane & 15, lmh = (lane >> 4) << 3;
    const int rowBase = blockIdx.y * 128;
    const int colBase = blockIdx.x * 128;

    float acc[2][8][4];
#pragma unroll
    for (int mi = 0; mi < 2; mi++)
#pragma unroll
        for (int nj = 0; nj < 8; nj++)
#pragma unroll
            for (int q = 0; q < 4; q++) acc[mi][nj][q] = 0.f;

    auto loadTile = [&](int k0, int st) {
        bf16* As = dsm + st * STG;
        bf16* Bs = As + 128 * LDA;
#pragma unroll
        for (int i = 0; i < 4; i++) {              // A: 128 rows x 64 bf16
            int lin = tid + i * 256;
            int r = lin >> 3, kc = (lin & 7) << 3;
            cp16(As + r * LDA + kc, Ab + (size_t)(rowBase + r) * NN + k0 + kc);
        }
#pragma unroll
        for (int i = 0; i < 4; i++) {              // B: 64 rows x 128 bf16
            int lin = tid + i * 256;
            int kk = lin >> 4, c8 = (lin & 15) << 3;
            cp16(Bs + kk * LDB + c8, Bb + (size_t)(k0 + kk) * NN + colBase + c8);
        }
        asm volatile("cp.async.commit_group;");
    };

    loadTile(0, 0);
    for (int t = 0; t < 8; t++) {                  // k-tiles of 64
        if (t < 7) {
            loadTile((t + 1) * 64, (t + 1) & 1);
            asm volatile("cp.async.wait_group 1;");
        } else {
            asm volatile("cp.async.wait_group 0;");
        }
        __syncthreads();
        const bf16* As = dsm + (t & 1) * STG;
        const bf16* Bs = As + 128 * LDA;
#pragma unroll
        for (int kk = 0; kk < 64; kk += 16) {
            uint32_t a[2][4], bq[4][4];
#pragma unroll
            for (int mi = 0; mi < 2; mi++) {
                int r = wr * 32 + mi * 16 + lml;
                LDSM4(a[mi], smaddr(As + r * LDA + kk + lmh));
            }
#pragma unroll
            for (int njp = 0; njp < 4; njp++)
                LDSM4T(bq[njp], smaddr(Bs + (kk + lml) * LDB + wc * 64 + njp * 16 + lmh));
#pragma unroll
            for (int mi = 0; mi < 2; mi++)
#pragma unroll
                for (int njp = 0; njp < 4; njp++) {
                    MMA_BF16(acc[mi][2*njp],   a[mi], (bq[njp]));
                    MMA_BF16(acc[mi][2*njp+1], a[mi], (bq[njp]+2));
                }
        }
        __syncthreads();
    }

#pragma unroll
    for (int mi = 0; mi < 2; mi++) {
        int r0 = rowBase + wr * 32 + mi * 16 + lr;
#pragma unroll
        for (int nj = 0; nj < 8; nj++) {
            int col = colBase + wc * 64 + nj * 8 + 2 * lq;
            *(bf162*)(Cb + (size_t)r0 * NN + col) =
                __floats2bfloat162_rn(acc[mi][nj][0], acc[mi][nj][1]);
            *(bf162*)(Cb + (size_t)(r0 + 8) * NN + col) =
                __floats2bfloat162_rn(acc[mi][nj][2], acc[mi][nj][3]);
        }
    }
}

// ---------------- finalize: BN params + analytic extractor -------------------
__global__ void k_finalize(float* __restrict__ ST,
                           const float* __restrict__ g, const float* __restrict__ b,
                           const float* __restrict__ w1, const float* __restrict__ b1,
                           const float* __restrict__ w2, const float* __restrict__ w3,
                           float* __restrict__ acc) {
    int h = threadIdx.x;                               // 64 threads
    __shared__ float str[64], stot[64], osh[64];
    float sum = ST[ST_SUM + h], sq = ST[ST_SQ + h], tr = ST[ST_TR + h];
    float m   = sum / (float)NP;
    float var = sq / (float)NP - m * m;
    float s   = g[h] * rsqrtf(var + 1e-5f);
    float t   = b[h] - m * s;
    ST[ST_S + h] = s; ST[ST_T + h] = t;
    ST[ST_SUM + h] = 0.f; ST[ST_SQ + h] = 0.f; ST[ST_TR + h] = 0.f;
    str[h]  = tr * s + 512.f * t;
    stot[h] = sum * s + (float)NP * t;
    __syncthreads();
    float o = b1[h];
    for (int c = 0; c < 64; c++) {
        float trc = str[c];
        float sc  = (stot[c] - trc) / (512.f * 511.f);
        o += w1[h * 64 + c] * (trc / 512.f) + w2[h * 64 + c] * sc;
    }
    osh[h] = o; __syncthreads();
    float a = o;
    for (int k = 0; k < 64; k++) a += w3[h * 64 + k] * fmaxf(osh[k], 0.f);
    acc[h] += a;
}

// ---------------- head -------------------------------------------------------
__global__ void k_head(const float* __restrict__ acc,
                       const float* __restrict__ ac_w, const float* __restrict__ ac_b,
                       const float* __restrict__ fl_w, const float* __restrict__ fl_b,
                       float* __restrict__ out) {
    __shared__ float o[64], t[64], lg[10];
    int h = threadIdx.x;
    o[h] = fmaxf(acc[h], 0.f) / (float)NL;
    __syncthreads();
    float s = ac_b[h];
    for (int k = 0; k < 64; k++) s += ac_w[h * 64 + k] * o[k];
    t[h] = o[h] + fmaxf(s, 0.f);
    __syncthreads();
    if (h < 10) {
        float l = fl_b[h];
        for (int k = 0; k < 64; k++) l += fl_w[h * 64 + k] * t[k];
        lg[h] = l;
    }
    __syncthreads();
    if (h < 10) {
        float m = -1e30f;
        for (int i = 0; i < 10; i++) m = fmaxf(m, lg[i]);
        float se = 0.f;
        for (int i = 0; i < 10; i++) se += expf(lg[i] - m);
        out[h] = lg[h] - m - logf(se);
    }
}

// ---------------- launch -----------------------------------------------------
extern "C" void kernel_launch(void* const* d_in, const int* in_sizes, int n_in,
                              void* d_out, int out_size) {
    const float* x     = (const float*)d_in[0];
    const int*   ei    = (const int*)  d_in[1];
    const float* np1_w = (const float*)d_in[2];
    const float* np1_b = (const float*)d_in[3];
    const float* np2_w = (const float*)d_in[4];
    const float* np3_w = (const float*)d_in[5];
    const float* c0m1w = (const float*)d_in[6];
    const float* c0m1b = (const float*)d_in[7];
    const float* c0m2w = (const float*)d_in[8];
    const float* c0m2b = (const float*)d_in[9];
    const float* c0m4w = (const float*)d_in[10];
    const float* c0m4b = (const float*)d_in[11];
    const float* cm1w  = (const float*)d_in[12];
    const float* cm1b  = (const float*)d_in[13];
    const float* cm2w  = (const float*)d_in[14];
    const float* cm2b  = (const float*)d_in[15];
    const float* cm4w  = (const float*)d_in[16];
    const float* cm4b  = (const float*)d_in[17];
    const float* bn_g  = (const float*)d_in[18];
    const float* bn_b  = (const float*)d_in[19];
    const float* fe1w  = (const float*)d_in[20];
    const float* fe1b  = (const float*)d_in[21];
    const float* fe2w  = (const float*)d_in[22];
    const float* fe3w  = (const float*)d_in[23];
    const float* ac_w  = (const float*)d_in[24];
    const float* ac_b  = (const float*)d_in[25];
    const float* fl_w  = (const float*)d_in[26];
    const float* fl_b  = (const float*)d_in[27];

    float *U, *ST, *AC;
    bf16 *Ub, *V0, *V1, *O1, *O2, *M;
    cudaGetSymbolAddress((void**)&U,  g_U);
    cudaGetSymbolAddress((void**)&Ub, g_Ub);
    cudaGetSymbolAddress((void**)&V0, g_V0);
    cudaGetSymbolAddress((void**)&V1, g_V1);
    cudaGetSymbolAddress((void**)&O1, g_O1);
    cudaGetSymbolAddress((void**)&O2, g_O2);
    cudaGetSymbolAddress((void**)&M,  g_M);
    cudaGetSymbolAddress((void**)&ST, g_ST);
    cudaGetSymbolAddress((void**)&AC, g_AC);

    static bool attr_done = false;
    if (!attr_done) {
        cudaFuncSetAttribute(k_mma,   cudaFuncAttributeMaxDynamicSharedMemorySize, 2 * STG * 2);
        cudaFuncSetAttribute(k_mixAB, cudaFuncAttributeMaxDynamicSharedMemorySize, 64 * 1024);
        cudaFuncSetAttribute(k_mix4,  cudaFuncAttributeMaxDynamicSharedMemorySize, 64 * 1024);
        attr_done = true;
    }

    k_zero<<<(32u * NP) / 256, 256>>>(U, AC, ST);
    k_scatter<<<(EE * 32) / 256, 256>>>(x, ei, U);

    k_ext_stats<<<TWOF, 256>>>(U, ST + ST_ATR, Ub);
    k_ext_combine<<<1, 64>>>(ST + ST_ATR, np1_w, np1_b, np2_w, np3_w, TWOF, AC);

    const bf16* cur = Ub;
    for (int l = 0; l < NL; l++) {
        const int Cin = l ? 64 : TWOF;
        const int fold = (l > 0) ? 1 : 0;
        const float* m1w = l ? cm1w + (l - 1) * 64 * 64  : c0m1w;
        const float* m1b = l ? cm1b + (l - 1) * 64       : c0m1b;
        const float* m2w = l ? cm2w + (l - 1) * 64 * 64  : c0m2w;
        const float* m2b = l ? cm2b + (l - 1) * 64       : c0m2b;
        const float* m4w = l ? cm4w + (l - 1) * 64 * 128 : c0m4w;
        const float* m4b = l ? cm4b + (l - 1) * 64       : c0m4b;

        int ldab = Cin + 8;
        size_t shAB = (size_t)(2 * 64 * ldab + 32 * 136) * 2 + 2 * 64 * 4;
        k_mixAB<<<2048, 256, shAB>>>(cur, Cin, m1w, m1b, m2w, m2b, ST, fold, O1, O2);

        k_mma<<<dim3(4, 4, 64), 256, 2 * STG * 2>>>(O1, O2, M);

        bf16* nxt = (l == 0) ? V0 : ((l == 1) ? V1 : nullptr);
        int ld4 = 64 + Cin + 8;
        size_t sh4 = (size_t)(64 * ld4 + 32 * 136) * 2 + (64 + 192) * 4;
        k_mix4<<<2048, 256, sh4>>>(M, cur, Cin, m4w, m4b, fold, nxt, ST);

        k_finalize<<<1, 64>>>(ST, bn_g + 64 * l, bn_b + 64 * l,
                              fe1w + l * 64 * 64, fe1b + l * 64,
                              fe2w + l * 64 * 64, fe3w + l * 64 * 64, AC);

        cur = nxt;
    }

    k_head<<<1, 64>>>(AC, ac_w, ac_b, fl_w, fl_b, (float*)d_out);
}